// round 15
// baseline (speedup 1.0000x reference)
#include <cuda_runtime.h>
#include <stdint.h>

#define GRID_N   8
#define L_SITES  64
#define S_SIZE   9
#define N_PLAQ   64
#define LOCAL_D  2
#define M_DIM    128
#define BATCH    2048
#define N_PAT    512
#define ROW_STR  132        // padded row stride (floats)
#define SP_STR   132        // padded sPart stride (128 pats + 4)

#define TABLE_BYTES (N_PLAQ * N_PAT * 4)   // 131072 = 128 KB

// T[p][pat], pat bit s = occupancy of window site s. 128 KB, L2-resident.
__device__ float g_table[N_PLAQ * N_PAT];

// ---------------------------------------------------------------------------
// Kernel 1: build table. Block = (plaquette, s7s8-quarter): 256 blocks.
// (Unchanged from R14 — measured fast.)
// ---------------------------------------------------------------------------
__global__ __launch_bounds__(512, 2)
void build_kernel(const float* __restrict__ eps)
{
    const int tid = threadIdx.x;
    const int p   = blockIdx.x >> 2;      // plaquette
    const int q   = blockIdx.x & 3;       // (s8<<1)|s7 occupancy bits

    __shared__ __align__(16) float sSA[8 * ROW_STR];   // [s4..s6][m], s7,s8 folded
    __shared__ __align__(16) float sSB[16 * ROW_STR];  // [s0..s3][m]
    __shared__ float sPart[16 * SP_STR];               // k-chunk partials

    {
        const int m    = tid & 127;
        const int part = tid >> 7;        // 0,1: SB 8 rows each; 2,3: SA 4 rows
        const float* e0p = eps + ((size_t)(0 * N_PLAQ + p) * M_DIM + m) * S_SIZE;
        const float* e1p = eps + ((size_t)(1 * N_PLAQ + p) * M_DIM + m) * S_SIZE;
        float a0[S_SIZE], a1[S_SIZE];
        #pragma unroll
        for (int s = 0; s < S_SIZE; s++) { a0[s] = __ldg(e0p + s); a1[s] = __ldg(e1p + s); }

        if (part < 2) {
            const int base = part * 8;
            #pragma unroll
            for (int k = 0; k < 8; k++) {
                const int lo = base + k;
                float v = ((lo & 1) ? a1[0] : a0[0]);
                v *= ((lo & 2) ? a1[1] : a0[1]);
                v *= ((lo & 4) ? a1[2] : a0[2]);
                v *= ((lo & 8) ? a1[3] : a0[3]);
                sSB[lo * ROW_STR + m] = v;
            }
        } else {
            const int base = (part - 2) * 4;
            const float f78 = ((q & 1) ? a1[7] : a0[7]) * ((q & 2) ? a1[8] : a0[8]);
            #pragma unroll
            for (int k = 0; k < 4; k++) {
                const int h3 = base + k;              // bits s4..s6
                float v = ((h3 & 1) ? a1[4] : a0[4]);
                v *= ((h3 & 2) ? a1[5] : a0[5]);
                v *= ((h3 & 4) ? a1[6] : a0[6]);
                sSA[h3 * ROW_STR + m] = v * f78;
            }
        }
    }
    __syncthreads();

    {
        const int quad = tid >> 4;            // 0..31 -> (hi pair, lo pair)
        const int kc   = tid & 15;            // 8-float chunk of m
        const int hi0  = (quad >> 3) * 2;     // 0,2,4,6   (s4..s6 pair)
        const int lo0  = (quad & 7) * 2;      // 0,2,..,14 (s0..s3 pair)
        const float4* A0 = reinterpret_cast<const float4*>(sSA + hi0 * ROW_STR + kc * 8);
        const float4* A1 = reinterpret_cast<const float4*>(sSA + (hi0 + 1) * ROW_STR + kc * 8);
        const float4* B0 = reinterpret_cast<const float4*>(sSB + lo0 * ROW_STR + kc * 8);
        const float4* B1 = reinterpret_cast<const float4*>(sSB + (lo0 + 1) * ROW_STR + kc * 8);

        float a00 = 0.f, a01 = 0.f, a10 = 0.f, a11 = 0.f;
        #pragma unroll
        for (int i = 0; i < 2; i++) {
            const float4 x0 = A0[i], x1 = A1[i];
            const float4 y0 = B0[i], y1 = B1[i];
            a00 += x0.x*y0.x + x0.y*y0.y + x0.z*y0.z + x0.w*y0.w;
            a01 += x0.x*y1.x + x0.y*y1.y + x0.z*y1.z + x0.w*y1.w;
            a10 += x1.x*y0.x + x1.y*y0.y + x1.z*y0.z + x1.w*y0.w;
            a11 += x1.x*y1.x + x1.y*y1.y + x1.z*y1.z + x1.w*y1.w;
        }
        float* dst = sPart + kc * SP_STR;
        dst[(hi0    ) * 16 + lo0    ] = a00;
        dst[(hi0    ) * 16 + lo0 + 1] = a01;
        dst[(hi0 + 1) * 16 + lo0    ] = a10;
        dst[(hi0 + 1) * 16 + lo0 + 1] = a11;
    }
    __syncthreads();

    if (tid < 128) {
        float v = 0.0f;
        #pragma unroll
        for (int kc = 0; kc < 16; kc++) v += sPart[kc * SP_STR + tid];
        g_table[p * N_PAT + q * 128 + tid] = v;   // pat = (q<<7)|tid
    }
}

// ---------------------------------------------------------------------------
// Kernel 2: STAGED lookup. 64 blocks x 512 threads; each block copies the
// full 128 KB table into dynamic shared memory with coalesced float4 loads
// (kills the 32-way LDG sector fragmentation), then serves 32 batches with
// LDS gathers (~4-way bank conflicts instead of 32 sectors per load).
// ---------------------------------------------------------------------------
#define LKB_BLOCKS 64
#define LKB_BATCH  (BATCH / LKB_BLOCKS)   // 32 batches per block

__global__ __launch_bounds__(512, 1)
void lookup_kernel(const int* __restrict__ inputs, float* __restrict__ out)
{
    extern __shared__ __align__(16) float sTab[];   // 128 KB: [p][pat]

    const int tid  = threadIdx.x;
    const int lane = tid & 31;
    const int warp = tid >> 5;

    // ---- Stage table: coalesced, 16 float4 per thread ---------------------
    {
        const float4* src = reinterpret_cast<const float4*>(g_table);
        float4*       dst = reinterpret_cast<float4*>(sTab);
        #pragma unroll
        for (int i = 0; i < (N_PLAQ * N_PAT / 4) / 512; i++)
            dst[i * 512 + tid] = __ldg(src + i * 512 + tid);
    }
    __syncthreads();

    // ---- Serve 32 batches: 2 per warp -------------------------------------
    #pragma unroll
    for (int sub = 0; sub < 2; sub++) {
        const int b = blockIdx.x * LKB_BATCH + warp * 2 + sub;

        const int* row = inputs + (size_t)b * L_SITES;
        const unsigned mlo = __ballot_sync(0xFFFFFFFFu, row[lane]      & 1);
        const unsigned mhi = __ballot_sync(0xFFFFFFFFu, row[lane + 32] & 1);

        float acc = 0.0f;
        #pragma unroll
        for (int pp = 0; pp < 2; pp++) {
            const int p = lane + 32 * pp;
            const int i = p >> 3;
            const int j = p & 7;
            int pat = 0;
            #pragma unroll
            for (int di = 0; di < 3; di++) {
                const int r = (i + di) & 7;
                unsigned rb = (((r < 4) ? mlo : mhi) >> ((r & 3) * 8)) & 0xFFu;
                const unsigned dup = rb | (rb << 8);      // torus wraparound
                pat |= (int)((dup >> j) & 7u) << (3 * di);
            }
            acc += sTab[(p << 9) + pat];
        }

        #pragma unroll
        for (int off = 16; off > 0; off >>= 1)
            acc += __shfl_xor_sync(0xFFFFFFFFu, acc, off);

        if (lane == 0) out[b] = acc;
    }
}

// ---------------------------------------------------------------------------
extern "C" void kernel_launch(void* const* d_in, const int* in_sizes, int n_in,
                              void* d_out, int out_size)
{
    // Identify inputs by element count (all distinct):
    //   inputs: 2048*64 = 131072 (int32), plaquettes: 576 (int32, unused —
    //   window indices are arithmetically fixed), epsilon: 147456 (float32)
    const int*   inputs = nullptr;
    const float* eps    = nullptr;
    for (int i = 0; i < n_in; i++) {
        if      (in_sizes[i] == BATCH * L_SITES) inputs = (const int*)d_in[i];
        else if (in_sizes[i] == LOCAL_D * N_PLAQ * M_DIM * S_SIZE)
                                                 eps    = (const float*)d_in[i];
    }
    float* out = (float*)d_out;

    // Opt in to 128 KB dynamic smem for the staged lookup (idempotent).
    static int attr_set = 0;
    if (!attr_set) {
        cudaFuncSetAttribute(lookup_kernel,
                             cudaFuncAttributeMaxDynamicSharedMemorySize,
                             TABLE_BYTES);
        attr_set = 1;
    }

    build_kernel<<<N_PLAQ * 4, 512>>>(eps);
    lookup_kernel<<<LKB_BLOCKS, 512, TABLE_BYTES>>>(inputs, out);
}